// round 4
// baseline (speedup 1.0000x reference)
#include <cuda_runtime.h>
#include <math.h>

#define NN 100000
#define NE 3200000
#define SLOPE 0.01f

// ---------------- scratch (device globals; no allocation allowed) ----------
__device__ __align__(16) int   g_cnt   [NN];
__device__ __align__(16) int   g_rowptr[NN + 1];
__device__ __align__(16) int   g_next  [NN];
__device__ __align__(16) int   g_bsum  [32];
__device__ __align__(16) int   g_srcA  [NE];
__device__ __align__(16) int   g_dstA  [NE];
__device__ __align__(16) int   g_csr   [NE];
__device__ __align__(16) float g_dinv  [NN];
__device__ __align__(16) float g_h     [NN*16];
__device__ __align__(16) float g_xw    [NN*16];
__device__ float g_W[2*256];
__device__ int   g_is64;

__device__ __forceinline__ float lrelu(float v){ return v > 0.f ? v : SLOPE*v; }
__device__ __forceinline__ int   clampi(int v){ return v < 0 ? 0 : (v >= NN ? NN-1 : v); }

// ---------------- dtype detect: int64 vs int32 edge_index -------------------
// If the buffer is int64 little-endian with values < 2^31, every odd 32-bit
// word is zero.  If it is int32, odd words are random node ids (mostly != 0).
__global__ void k_detect(const int* __restrict__ ei32){
    __shared__ int any;
    if (threadIdx.x == 0) any = 0;
    __syncthreads();
    int e = threadIdx.x;                      // 1024 threads
    int v = ei32[2*e + 1] | ei32[2*(e + 1024) + 1] | ei32[2*(e + 2048) + 1];
    if (v) atomicOr(&any, 1);
    __syncthreads();
    if (threadIdx.x == 0) g_is64 = (any == 0) ? 1 : 0;
}

// ---------------- hypernetwork: W[l] = wt_W[l] @ mem[l] + wt_b[l] ----------
__global__ void k_hyper(const float* __restrict__ bih, const float* __restrict__ bhh,
                        const float* __restrict__ wtW, const float* __restrict__ wtb){
    int t = threadIdx.x;                 // 512 threads: (l, j)
    int l = t >> 8, j = t & 255;
    float mem[16];
#pragma unroll
    for (int m = 0; m < 16; m++){
        float r = 1.f/(1.f + expf(-(bih[l*48 + m]      + bhh[l*48 + m])));
        float z = 1.f/(1.f + expf(-(bih[l*48 + 16 + m] + bhh[l*48 + 16 + m])));
        float n = tanhf(bih[l*48 + 32 + m] + r*bhh[l*48 + 32 + m]);
        mem[m] = (1.f - z) * n;
    }
    float acc = wtb[l*256 + j];
#pragma unroll
    for (int m = 0; m < 16; m++) acc += wtW[(l*256 + j)*16 + m] * mem[m];
    g_W[l*256 + j] = acc;
}

// ---------------- degree count ----------------------------------------------
__global__ void k_cnt0(){
    int i = blockIdx.x*blockDim.x + threadIdx.x;
    if (i < NN) g_cnt[i] = 0;
}
__global__ void k_edges(const int* __restrict__ ei32){
    int e = blockIdx.x*blockDim.x + threadIdx.x;
    if (e >= NE) return;
    int s, d;
    if (g_is64){                       // int64 layout: word 2*idx is the low half
        s = ei32[2*(size_t)e];
        d = ei32[2*((size_t)NE + e)];
    } else {                           // int32 layout
        s = ei32[e];
        d = ei32[NE + e];
    }
    s = clampi(s); d = clampi(d);
    g_srcA[e] = s; g_dstA[e] = d;
    atomicAdd(&g_cnt[d], 1);
}
__global__ void k_dinv(){
    int i = blockIdx.x*blockDim.x + threadIdx.x;
    if (i < NN) g_dinv[i] = rsqrtf((float)g_cnt[i] + 1.0f);  // +1 self loop
}

// ---------------- exclusive scan over g_cnt -> g_rowptr ----------------------
__global__ void k_scan1(){
    __shared__ int ts[512];
    int b = blockIdx.x, t = threadIdx.x;
    int base = b*4096 + t*8;
    int v[8]; int s = 0;
#pragma unroll
    for (int k = 0; k < 8; k++){
        v[k] = (base + k < NN) ? g_cnt[base + k] : 0;
        s += v[k];
    }
    ts[t] = s; __syncthreads();
#pragma unroll
    for (int off = 1; off < 512; off <<= 1){
        int y = (t >= off) ? ts[t - off] : 0;
        __syncthreads();
        ts[t] += y;
        __syncthreads();
    }
    if (t == 511) g_bsum[b] = ts[511];
    int run = ts[t] - s;   // exclusive
#pragma unroll
    for (int k = 0; k < 8; k++){
        if (base + k < NN) g_rowptr[base + k] = run;
        run += v[k];
    }
}
__global__ void k_scan2(int nb){
    if (threadIdx.x == 0){
        int run = 0;
        for (int i = 0; i < nb; i++){ int v = g_bsum[i]; g_bsum[i] = run; run += v; }
    }
}
__global__ void k_scan3(){
    int i = blockIdx.x*blockDim.x + threadIdx.x;
    if (i < NN){
        int r = g_rowptr[i] + g_bsum[i >> 12];
        g_rowptr[i] = r;
        g_next[i]   = r;
    }
    if (i == 0) g_rowptr[NN] = NE;
}

// ---------------- CSR fill ----------------------------------------------------
__global__ void k_fill(){
    int e = blockIdx.x*blockDim.x + threadIdx.x;
    if (e < NE){
        int d = g_dstA[e];
        int pos = atomicAdd(&g_next[d], 1);
        if (pos >= 0 && pos < NE) g_csr[pos] = g_srcA[e];
    }
}

// ---------------- fused preprocess MLP: 128 -> 256 -> 16 ---------------------
#define P_W1 0         // 32768: blocked w1v[j*256+r] = W1[r][4j..4j+3]
#define P_B1 32768     // 256
#define P_W2 33024     // 256*17 padded transpose: w2t[k*17+o] = W2[o][k]
#define P_B2 37376     // 16
#define P_X  37392     // 4 nodes x 128
#define P_H1 37904     // 4 x 256
#define P_R  38928     // 4 x 256
#define PRE_SMEM_FLOATS 39952
#define PRE_SMEM_BYTES  (PRE_SMEM_FLOATS*4)

__global__ void __launch_bounds__(256, 1)
k_pre(const float* __restrict__ x,
      const float* __restrict__ p1W, const float* __restrict__ p1b,
      const float* __restrict__ p2W, const float* __restrict__ p2b){
    extern __shared__ float sm[];
    int t = threadIdx.x;

    // stage weights once
    {
        float4* w1v = (float4*)(sm + P_W1);
        const float4* p1W4 = (const float4*)p1W;
        for (int i = t; i < 8192; i += 256){
            int j = i >> 8, r = i & 255;
            w1v[i] = p1W4[r*32 + j];
        }
        sm[P_B1 + t] = p1b[t];
        for (int i = t; i < 4096; i += 256){
            int k = i >> 4, o = i & 15;
            sm[P_W2 + k*17 + o] = p2W[o*256 + k];
        }
        if (t < 16) sm[P_B2 + t] = p2b[t];
    }
    __syncthreads();

    const float4* w1v = (const float4*)(sm + P_W1);
    const float4* xq  = (const float4*)(sm + P_X);
    float bb = sm[P_B1 + t];

    for (int base = blockIdx.x*4; base < NN; base += gridDim.x*4){
        // stage x for 4 nodes
        for (int i = t; i < 512; i += 256){
            int n = i >> 7, k = i & 127;
            int node = base + n;
            sm[P_X + n*128 + k] = (node < NN) ? x[(size_t)node*128 + k] : 0.f;
        }
        __syncthreads();

        // layer 1: each thread = one of 256 outputs, 4 nodes
        float a0 = bb, a1 = bb, a2 = bb, a3 = bb;
#pragma unroll 8
        for (int j = 0; j < 32; j++){
            float4 w  = w1v[j*256 + t];
            float4 x0 = xq[0*32 + j];
            float4 x1 = xq[1*32 + j];
            float4 x2 = xq[2*32 + j];
            float4 x3 = xq[3*32 + j];
            a0 += w.x*x0.x; a0 += w.y*x0.y; a0 += w.z*x0.z; a0 += w.w*x0.w;
            a1 += w.x*x1.x; a1 += w.y*x1.y; a1 += w.z*x1.z; a1 += w.w*x1.w;
            a2 += w.x*x2.x; a2 += w.y*x2.y; a2 += w.z*x2.z; a2 += w.w*x2.w;
            a3 += w.x*x3.x; a3 += w.y*x3.y; a3 += w.z*x3.z; a3 += w.w*x3.w;
        }
        sm[P_H1 + 0*256 + t] = lrelu(a0);
        sm[P_H1 + 1*256 + t] = lrelu(a1);
        sm[P_H1 + 2*256 + t] = lrelu(a2);
        sm[P_H1 + 3*256 + t] = lrelu(a3);
        __syncthreads();

        // layer 2 partials: o = t&15, part = t>>4 (16 parts of 16 k each)
        {
            int o = t & 15, part = t >> 4;
            float p0 = 0.f, p1 = 0.f, p2 = 0.f, p3 = 0.f;
#pragma unroll
            for (int kk = 0; kk < 16; kk++){
                int k = part*16 + kk;
                float w2s = sm[P_W2 + k*17 + o];
                p0 += sm[P_H1 + 0*256 + k]*w2s;
                p1 += sm[P_H1 + 1*256 + k]*w2s;
                p2 += sm[P_H1 + 2*256 + k]*w2s;
                p3 += sm[P_H1 + 3*256 + k]*w2s;
            }
            sm[P_R + 0*256 + part*16 + o] = p0;
            sm[P_R + 1*256 + part*16 + o] = p1;
            sm[P_R + 2*256 + part*16 + o] = p2;
            sm[P_R + 3*256 + part*16 + o] = p3;
        }
        __syncthreads();

        if (t < 64){
            int n = t >> 4, o = t & 15;
            int node = base + n;
            if (node < NN){
                float s = 0.f;
#pragma unroll
                for (int p = 0; p < 16; p++) s += sm[P_R + n*256 + p*16 + o];
                g_h[(size_t)node*16 + o] = lrelu(s + sm[P_B2 + o]);
            }
        }
        __syncthreads();
    }
}

// ---------------- per-layer: xw' = (h@W.T) * dinv -----------------------------
__global__ void k_xw(int l){
    __shared__ float Ws[256];
    if (threadIdx.x < 256) Ws[threadIdx.x] = g_W[l*256 + threadIdx.x];
    __syncthreads();
    int n = blockIdx.x*blockDim.x + threadIdx.x;
    if (n >= NN) return;
    const float4* h4 = (const float4*)g_h;
    float4 a = h4[n*4+0], b = h4[n*4+1], c = h4[n*4+2], d = h4[n*4+3];
    float hv[16] = {a.x,a.y,a.z,a.w, b.x,b.y,b.z,b.w,
                    c.x,c.y,c.z,c.w, d.x,d.y,d.z,d.w};
    float di = g_dinv[n];
    float4* xw4 = (float4*)g_xw;
#pragma unroll
    for (int q = 0; q < 4; q++){
        float4 v;
        float* vp = (float*)&v;
#pragma unroll
        for (int r = 0; r < 4; r++){
            int o = q*4 + r;
            float acc = 0.f;
#pragma unroll
            for (int i = 0; i < 16; i++) acc += hv[i]*Ws[o*16 + i];
            vp[r] = acc * di;
        }
        xw4[n*4 + q] = v;
    }
}

// ---------------- gather: h[d] = lrelu(dinv[d]*(sum xw'[s] + xw'[d]) + b) -----
__global__ void __launch_bounds__(256)
k_gather(const float* __restrict__ gcnb, int l){
    int tid = blockIdx.x*blockDim.x + threadIdx.x;
    int node = tid >> 4;
    int o    = tid & 15;
    if (node >= NN) return;
    int beg = g_rowptr[node], end = g_rowptr[node + 1];
    float acc = g_xw[(size_t)node*16 + o];                 // self loop
    int j = beg;
    for (; j + 3 < end; j += 4){
        int s0 = g_csr[j], s1 = g_csr[j+1], s2 = g_csr[j+2], s3 = g_csr[j+3];
        acc += g_xw[(size_t)s0*16 + o];
        acc += g_xw[(size_t)s1*16 + o];
        acc += g_xw[(size_t)s2*16 + o];
        acc += g_xw[(size_t)s3*16 + o];
    }
    for (; j < end; j++) acc += g_xw[(size_t)g_csr[j]*16 + o];
    float v = g_dinv[node]*acc + gcnb[l*16 + o];
    g_h[(size_t)node*16 + o] = lrelu(v);
}

// ---------------- post heads ---------------------------------------------------
__global__ void k_post(const float* __restrict__ p1W, const float* __restrict__ p1b,
                       const float* __restrict__ paW, const float* __restrict__ pab,
                       float* __restrict__ out, int out_size){
    __shared__ float ws[16], wa[16];
    __shared__ float bs, ba;
    if (threadIdx.x < 16){
        ws[threadIdx.x] = p1W[threadIdx.x] + p1W[16 + threadIdx.x];
        wa[threadIdx.x] = paW[threadIdx.x];
    }
    if (threadIdx.x == 0){ bs = p1b[0] + p1b[1]; ba = pab[0]; }
    __syncthreads();
    int n = blockIdx.x*blockDim.x + threadIdx.x;
    if (n >= NN) return;
    const float4* h4 = (const float4*)g_h;
    float4 a = h4[n*4+0], b = h4[n*4+1], c = h4[n*4+2], d = h4[n*4+3];
    float hv[16] = {a.x,a.y,a.z,a.w, b.x,b.y,b.z,b.w,
                    c.x,c.y,c.z,c.w, d.x,d.y,d.z,d.w};
    float so = bs, sa = ba;
#pragma unroll
    for (int i = 0; i < 16; i++){ so += hv[i]*ws[i]; sa += hv[i]*wa[i]; }
    out[n] = so;
    if (out_size >= 2*NN) out[NN + n] = sa;
    if (out_size >= 18*NN){
        float4* o4 = (float4*)(out + 2*NN);
        o4[n*4+0] = a; o4[n*4+1] = b; o4[n*4+2] = c; o4[n*4+3] = d;
    }
}

// ---------------- launch --------------------------------------------------------
extern "C" void kernel_launch(void* const* d_in, const int* in_sizes, int n_in,
                              void* d_out, int out_size){
    const float* x    = (const float*)d_in[0];
    const int*   ei32 = (const int*)d_in[1];     // dtype detected on device
    const float* p1W  = (const float*)d_in[2];
    const float* p1b  = (const float*)d_in[3];
    const float* p2W  = (const float*)d_in[4];
    const float* p2b  = (const float*)d_in[5];
    const float* bih  = (const float*)d_in[6];
    const float* bhh  = (const float*)d_in[7];
    const float* wtW  = (const float*)d_in[8];
    const float* wtb  = (const float*)d_in[9];
    const float* gcnb = (const float*)d_in[10];
    const float* po1W = (const float*)d_in[11];
    const float* po1b = (const float*)d_in[12];
    const float* poaW = (const float*)d_in[13];
    const float* poab = (const float*)d_in[14];
    float* out = (float*)d_out;

    cudaFuncSetAttribute(k_pre, cudaFuncAttributeMaxDynamicSharedMemorySize,
                         PRE_SMEM_BYTES);

    const int NB_N = (NN + 255)/256;
    const int NB_E = (NE + 255)/256;
    const int NB_SCAN = (NN + 4095)/4096;   // 25

    k_detect<<<1, 1024>>>(ei32);
    k_hyper <<<1, 512>>>(bih, bhh, wtW, wtb);
    k_cnt0  <<<NB_N, 256>>>();
    k_edges <<<NB_E, 256>>>(ei32);
    k_dinv  <<<NB_N, 256>>>();
    k_scan1 <<<NB_SCAN, 512>>>();
    k_scan2 <<<1, 32>>>(NB_SCAN);
    k_scan3 <<<NB_N, 256>>>();
    k_fill  <<<NB_E, 256>>>();
    k_pre   <<<148, 256, PRE_SMEM_BYTES>>>(x, p1W, p1b, p2W, p2b);

    for (int l = 0; l < 2; l++){
        k_xw     <<<NB_N, 256>>>(l);
        k_gather <<<(NN*16 + 255)/256, 256>>>(gcnb, l);
    }
    k_post<<<NB_N, 256>>>(po1W, po1b, poaW, poab, out, out_size);
}

// round 5
// speedup vs baseline: 1.3051x; 1.3051x over previous
#include <cuda_runtime.h>
#include <math.h>

#define NN 100000
#define NE 3200000
#define SLOPE 0.01f

// ---------------- scratch (device globals; no allocation allowed) ----------
__device__ __align__(16) int   g_cnt   [NN];
__device__ __align__(16) int   g_rowptr[NN + 1];
__device__ __align__(16) int   g_next  [NN];
__device__ __align__(16) int   g_bsum  [32];
__device__ __align__(16) int   g_srcA  [NE];
__device__ __align__(16) int   g_dstA  [NE];
__device__ __align__(16) int   g_csr   [NE];
__device__ __align__(16) float g_dinv  [NN];
__device__ __align__(16) float g_h     [NN*16];
__device__ __align__(16) float g_xw    [NN*16];
__device__ float g_W[2*256];
__device__ int   g_is64;

__device__ __forceinline__ float lrelu(float v){ return v > 0.f ? v : SLOPE*v; }
__device__ __forceinline__ int   clampi(int v){ return v < 0 ? 0 : (v >= NN ? NN-1 : v); }

// packed fp32x2 helpers (Blackwell) — exonerated: rounds 1-2 trapped in k_edges
__device__ __forceinline__ unsigned long long pk2(float a, float b){
    unsigned long long r;
    asm("mov.b64 %0, {%1, %2};" : "=l"(r) : "f"(a), "f"(b));
    return r;
}
__device__ __forceinline__ unsigned long long fma2(unsigned long long a,
                                                   unsigned long long b,
                                                   unsigned long long c){
    unsigned long long d;
    asm("fma.rn.f32x2 %0, %1, %2, %3;" : "=l"(d) : "l"(a), "l"(b), "l"(c));
    return d;
}
__device__ __forceinline__ float2 upk2(unsigned long long v){
    float2 r;
    asm("mov.b64 {%0, %1}, %2;" : "=f"(r.x), "=f"(r.y) : "l"(v));
    return r;
}

// ---------------- dtype detect: int64 vs int32 edge_index -------------------
__global__ void k_detect(const int* __restrict__ ei32){
    __shared__ int any;
    if (threadIdx.x == 0) any = 0;
    __syncthreads();
    int e = threadIdx.x;
    int v = ei32[2*e + 1] | ei32[2*(e + 1024) + 1] | ei32[2*(e + 2048) + 1];
    if (v) atomicOr(&any, 1);
    __syncthreads();
    if (threadIdx.x == 0) g_is64 = (any == 0) ? 1 : 0;
}

// ---------------- hypernetwork ------------------------------------------------
__global__ void k_hyper(const float* __restrict__ bih, const float* __restrict__ bhh,
                        const float* __restrict__ wtW, const float* __restrict__ wtb){
    int t = threadIdx.x;
    int l = t >> 8, j = t & 255;
    float mem[16];
#pragma unroll
    for (int m = 0; m < 16; m++){
        float r = 1.f/(1.f + expf(-(bih[l*48 + m]      + bhh[l*48 + m])));
        float z = 1.f/(1.f + expf(-(bih[l*48 + 16 + m] + bhh[l*48 + 16 + m])));
        float n = tanhf(bih[l*48 + 32 + m] + r*bhh[l*48 + 32 + m]);
        mem[m] = (1.f - z) * n;
    }
    float acc = wtb[l*256 + j];
#pragma unroll
    for (int m = 0; m < 16; m++) acc += wtW[(l*256 + j)*16 + m] * mem[m];
    g_W[l*256 + j] = acc;
}

// ---------------- degree count -------------------------------------------------
__global__ void k_cnt0(){
    int i = blockIdx.x*blockDim.x + threadIdx.x;
    if (i < NN) g_cnt[i] = 0;
}
// 2 edges per thread, 16B loads
__global__ void k_edges(const int* __restrict__ ei32){
    int p = blockIdx.x*blockDim.x + threadIdx.x;
    if (p >= NE/2) return;
    int s0, s1, d0, d1;
    if (g_is64){
        const longlong2* v = (const longlong2*)ei32;
        longlong2 sv = v[p];
        longlong2 dv = v[(NE >> 1) + p];
        s0 = (int)sv.x; s1 = (int)sv.y; d0 = (int)dv.x; d1 = (int)dv.y;
    } else {
        const int2* v = (const int2*)ei32;
        int2 sv = v[p];
        int2 dv = v[(NE >> 1) + p];
        s0 = sv.x; s1 = sv.y; d0 = dv.x; d1 = dv.y;
    }
    s0 = clampi(s0); s1 = clampi(s1); d0 = clampi(d0); d1 = clampi(d1);
    ((int2*)g_srcA)[p] = make_int2(s0, s1);
    ((int2*)g_dstA)[p] = make_int2(d0, d1);
    atomicAdd(&g_cnt[d0], 1);
    atomicAdd(&g_cnt[d1], 1);
}
__global__ void k_dinv(){
    int i = blockIdx.x*blockDim.x + threadIdx.x;
    if (i < NN) g_dinv[i] = rsqrtf((float)g_cnt[i] + 1.0f);
}

// ---------------- exclusive scan over g_cnt -> g_rowptr -------------------------
__global__ void k_scan1(){
    __shared__ int ts[512];
    int b = blockIdx.x, t = threadIdx.x;
    int base = b*4096 + t*8;
    int v[8]; int s = 0;
#pragma unroll
    for (int k = 0; k < 8; k++){
        v[k] = (base + k < NN) ? g_cnt[base + k] : 0;
        s += v[k];
    }
    ts[t] = s; __syncthreads();
#pragma unroll
    for (int off = 1; off < 512; off <<= 1){
        int y = (t >= off) ? ts[t - off] : 0;
        __syncthreads();
        ts[t] += y;
        __syncthreads();
    }
    if (t == 511) g_bsum[b] = ts[511];
    int run = ts[t] - s;
#pragma unroll
    for (int k = 0; k < 8; k++){
        if (base + k < NN) g_rowptr[base + k] = run;
        run += v[k];
    }
}
__global__ void k_scan2(int nb){
    if (threadIdx.x == 0){
        int run = 0;
        for (int i = 0; i < nb; i++){ int v = g_bsum[i]; g_bsum[i] = run; run += v; }
    }
}
__global__ void k_scan3(){
    int i = blockIdx.x*blockDim.x + threadIdx.x;
    if (i < NN){
        int r = g_rowptr[i] + g_bsum[i >> 12];
        g_rowptr[i] = r;
        g_next[i]   = r;
    }
    if (i == 0) g_rowptr[NN] = NE;
}

// ---------------- CSR fill --------------------------------------------------------
__global__ void k_fill(){
    int e = blockIdx.x*blockDim.x + threadIdx.x;
    if (e < NE){
        int d = g_dstA[e];
        int pos = atomicAdd(&g_next[d], 1);
        if (pos >= 0 && pos < NE) g_csr[pos] = g_srcA[e];
    }
}

// ---------------- fused preprocess MLP: 128 -> 256 -> 16 (f32x2 packed) -----------
#define P_W1 0         // 32768: blocked w1v[j*256+r] = W1[r][4j..4j+3]
#define P_B1 32768     // 256
#define P_W2 33024     // 256*17 padded transpose
#define P_B2 37376     // 16
#define P_X  37392     // 1024 floats = 512 float2 (4 node-pairs x 128 k)
#define P_H1 38416     // 8*256
#define P_R  40464     // 8*256
#define PRE_SMEM_FLOATS 42512
#define PRE_SMEM_BYTES  (PRE_SMEM_FLOATS*4)

__global__ void __launch_bounds__(512, 1)
k_pre(const float* __restrict__ x,
      const float* __restrict__ p1W, const float* __restrict__ p1b,
      const float* __restrict__ p2W, const float* __restrict__ p2b){
    extern __shared__ float sm[];
    int t = threadIdx.x;
    int g  = t >> 8;        // node group 0/1 (4 nodes each)
    int tt = t & 255;       // layer-1 output index

    {
        float4* w1v = (float4*)(sm + P_W1);
        const float4* p1W4 = (const float4*)p1W;
        for (int i = t; i < 8192; i += 512){
            int j = i >> 8, r = i & 255;
            w1v[i] = p1W4[r*32 + j];
        }
        for (int i = t; i < 256; i += 512) sm[P_B1 + i] = p1b[i];
        for (int i = t; i < 4096; i += 512){
            int k = i >> 4, o = i & 15;
            sm[P_W2 + k*17 + o] = p2W[o*256 + k];
        }
        if (t < 16) sm[P_B2 + t] = p2b[t];
    }
    __syncthreads();

    const float4*     wv  = (const float4*)(sm + P_W1);
    const ulonglong2* xq  = (const ulonglong2*)(sm + P_X);
    float2*           sxp = (float2*)(sm + P_X);
    float*            hb  = sm + P_H1;
    float*            sr  = sm + P_R;
    float bb = sm[P_B1 + tt];

    for (int base = blockIdx.x*8; base < NN; base += gridDim.x*8){
        // stage x for 8 nodes as (even,odd) pairs: sxp[p*128+k]
        {
            int p = t >> 7, k = t & 127;
            sxp[p*128 + k] = make_float2(x[(size_t)(base + 2*p    )*128 + k],
                                         x[(size_t)(base + 2*p + 1)*128 + k]);
        }
        __syncthreads();

        // layer 1: 4 nodes per group via packed f32x2 FMA
        unsigned long long a01 = pk2(bb, bb);
        unsigned long long a23 = a01;
        int pa = 2*g, pb = 2*g + 1;
#pragma unroll 8
        for (int j = 0; j < 32; j++){
            float4 w = wv[j*256 + tt];
            ulonglong2 ua  = xq[pa*64 + 2*j];
            ulonglong2 ua2 = xq[pa*64 + 2*j + 1];
            ulonglong2 ub  = xq[pb*64 + 2*j];
            ulonglong2 ub2 = xq[pb*64 + 2*j + 1];
            unsigned long long w0 = pk2(w.x, w.x), w1 = pk2(w.y, w.y);
            unsigned long long w2 = pk2(w.z, w.z), w3 = pk2(w.w, w.w);
            a01 = fma2(w0, ua.x,  a01);  a23 = fma2(w0, ub.x,  a23);
            a01 = fma2(w1, ua.y,  a01);  a23 = fma2(w1, ub.y,  a23);
            a01 = fma2(w2, ua2.x, a01);  a23 = fma2(w2, ub2.x, a23);
            a01 = fma2(w3, ua2.y, a01);  a23 = fma2(w3, ub2.y, a23);
        }
        float2 y01 = upk2(a01), y23 = upk2(a23);
        hb[(g*4 + 0)*256 + tt] = lrelu(y01.x);
        hb[(g*4 + 1)*256 + tt] = lrelu(y01.y);
        hb[(g*4 + 2)*256 + tt] = lrelu(y23.x);
        hb[(g*4 + 3)*256 + tt] = lrelu(y23.y);
        __syncthreads();

        // layer 2 partials
        {
            int o = tt & 15, part = tt >> 4;
            float p0 = 0.f, p1 = 0.f, p2 = 0.f, p3 = 0.f;
#pragma unroll
            for (int kk = 0; kk < 16; kk++){
                int k = part*16 + kk;
                float w2s = sm[P_W2 + k*17 + o];
                p0 += hb[(g*4 + 0)*256 + k]*w2s;
                p1 += hb[(g*4 + 1)*256 + k]*w2s;
                p2 += hb[(g*4 + 2)*256 + k]*w2s;
                p3 += hb[(g*4 + 3)*256 + k]*w2s;
            }
            sr[(g*4 + 0)*256 + part*16 + o] = p0;
            sr[(g*4 + 1)*256 + part*16 + o] = p1;
            sr[(g*4 + 2)*256 + part*16 + o] = p2;
            sr[(g*4 + 3)*256 + part*16 + o] = p3;
        }
        __syncthreads();

        if (t < 128){
            int n = t >> 4, o = t & 15;
            float s = 0.f;
#pragma unroll
            for (int p = 0; p < 16; p++) s += sr[n*256 + p*16 + o];
            g_h[(size_t)(base + n)*16 + o] = lrelu(s + sm[P_B2 + o]);
        }
        __syncthreads();
    }
}

// ---------------- per-layer: xw' = (h@W.T) * dinv ----------------------------------
__global__ void k_xw(int l){
    __shared__ float Ws[256];
    if (threadIdx.x < 256) Ws[threadIdx.x] = g_W[l*256 + threadIdx.x];
    __syncthreads();
    int n = blockIdx.x*blockDim.x + threadIdx.x;
    if (n >= NN) return;
    const float4* h4 = (const float4*)g_h;
    float4 a = h4[n*4+0], b = h4[n*4+1], c = h4[n*4+2], d = h4[n*4+3];
    float hv[16] = {a.x,a.y,a.z,a.w, b.x,b.y,b.z,b.w,
                    c.x,c.y,c.z,c.w, d.x,d.y,d.z,d.w};
    float di = g_dinv[n];
    float4* xw4 = (float4*)g_xw;
#pragma unroll
    for (int q = 0; q < 4; q++){
        float4 v;
        float* vp = (float*)&v;
#pragma unroll
        for (int r = 0; r < 4; r++){
            int o = q*4 + r;
            float acc = 0.f;
#pragma unroll
            for (int i = 0; i < 16; i++) acc += hv[i]*Ws[o*16 + i];
            vp[r] = acc * di;
        }
        xw4[n*4 + q] = v;
    }
}

// ---------------- gather: warp per node, float4 lanes, 8 edges/iter ---------------
__global__ void __launch_bounds__(256)
k_gather(const float* __restrict__ gcnb, int l){
    int warp = (blockIdx.x*blockDim.x + threadIdx.x) >> 5;
    int lane = threadIdx.x & 31;
    if (warp >= NN) return;
    int node = warp;
    int slot = lane >> 2;   // 0..7 : edge slot
    int cg   = lane & 3;    // component group (4 floats)
    int beg = g_rowptr[node], end = g_rowptr[node + 1];
    const float4* xw4 = (const float4*)g_xw;

    float4 acc;
    if (slot == 0) acc = xw4[(size_t)node*4 + cg];           // self loop
    else           acc = make_float4(0.f, 0.f, 0.f, 0.f);

    for (int j = beg + slot; j < end; j += 8){
        int s = g_csr[j];
        float4 v = xw4[(size_t)s*4 + cg];
        acc.x += v.x; acc.y += v.y; acc.z += v.z; acc.w += v.w;
    }
#pragma unroll
    for (int off = 4; off < 32; off <<= 1){
        acc.x += __shfl_xor_sync(0xffffffff, acc.x, off);
        acc.y += __shfl_xor_sync(0xffffffff, acc.y, off);
        acc.z += __shfl_xor_sync(0xffffffff, acc.z, off);
        acc.w += __shfl_xor_sync(0xffffffff, acc.w, off);
    }
    if (lane < 4){
        float di = g_dinv[node];
        const float* bp = gcnb + l*16 + cg*4;
        float4 r;
        r.x = lrelu(di*acc.x + bp[0]);
        r.y = lrelu(di*acc.y + bp[1]);
        r.z = lrelu(di*acc.z + bp[2]);
        r.w = lrelu(di*acc.w + bp[3]);
        ((float4*)g_h)[(size_t)node*4 + cg] = r;
    }
}

// ---------------- post heads --------------------------------------------------------
__global__ void k_post(const float* __restrict__ p1W, const float* __restrict__ p1b,
                       const float* __restrict__ paW, const float* __restrict__ pab,
                       float* __restrict__ out, int out_size){
    __shared__ float ws[16], wa[16];
    __shared__ float bs, ba;
    if (threadIdx.x < 16){
        ws[threadIdx.x] = p1W[threadIdx.x] + p1W[16 + threadIdx.x];
        wa[threadIdx.x] = paW[threadIdx.x];
    }
    if (threadIdx.x == 0){ bs = p1b[0] + p1b[1]; ba = pab[0]; }
    __syncthreads();
    int n = blockIdx.x*blockDim.x + threadIdx.x;
    if (n >= NN) return;
    const float4* h4 = (const float4*)g_h;
    float4 a = h4[n*4+0], b = h4[n*4+1], c = h4[n*4+2], d = h4[n*4+3];
    float hv[16] = {a.x,a.y,a.z,a.w, b.x,b.y,b.z,b.w,
                    c.x,c.y,c.z,c.w, d.x,d.y,d.z,d.w};
    float so = bs, sa = ba;
#pragma unroll
    for (int i = 0; i < 16; i++){ so += hv[i]*ws[i]; sa += hv[i]*wa[i]; }
    out[n] = so;
    if (out_size >= 2*NN) out[NN + n] = sa;
    if (out_size >= 18*NN){
        float4* o4 = (float4*)(out + 2*NN);
        o4[n*4+0] = a; o4[n*4+1] = b; o4[n*4+2] = c; o4[n*4+3] = d;
    }
}

// ---------------- launch ---------------------------------------------------------------
extern "C" void kernel_launch(void* const* d_in, const int* in_sizes, int n_in,
                              void* d_out, int out_size){
    const float* x    = (const float*)d_in[0];
    const int*   ei32 = (const int*)d_in[1];
    const float* p1W  = (const float*)d_in[2];
    const float* p1b  = (const float*)d_in[3];
    const float* p2W  = (const float*)d_in[4];
    const float* p2b  = (const float*)d_in[5];
    const float* bih  = (const float*)d_in[6];
    const float* bhh  = (const float*)d_in[7];
    const float* wtW  = (const float*)d_in[8];
    const float* wtb  = (const float*)d_in[9];
    const float* gcnb = (const float*)d_in[10];
    const float* po1W = (const float*)d_in[11];
    const float* po1b = (const float*)d_in[12];
    const float* poaW = (const float*)d_in[13];
    const float* poab = (const float*)d_in[14];
    float* out = (float*)d_out;

    cudaFuncSetAttribute(k_pre, cudaFuncAttributeMaxDynamicSharedMemorySize,
                         PRE_SMEM_BYTES);

    const int NB_N = (NN + 255)/256;
    const int NB_E = (NE + 255)/256;
    const int NB_E2 = (NE/2 + 255)/256;
    const int NB_SCAN = (NN + 4095)/4096;   // 25

    k_detect<<<1, 1024>>>(ei32);
    k_hyper <<<1, 512>>>(bih, bhh, wtW, wtb);
    k_cnt0  <<<NB_N, 256>>>();
    k_edges <<<NB_E2, 256>>>(ei32);
    k_dinv  <<<NB_N, 256>>>();
    k_scan1 <<<NB_SCAN, 512>>>();
    k_scan2 <<<1, 32>>>(NB_SCAN);
    k_scan3 <<<NB_N, 256>>>();
    k_fill  <<<NB_E, 256>>>();
    k_pre   <<<148, 512, PRE_SMEM_BYTES>>>(x, p1W, p1b, p2W, p2b);

    const int NB_G = (NN*32 + 255)/256;     // warp per node
    for (int l = 0; l < 2; l++){
        k_xw     <<<NB_N, 256>>>(l);
        k_gather <<<NB_G, 256>>>(gcnb, l);
    }
    k_post<<<NB_N, 256>>>(po1W, po1b, poaW, poab, out, out_size);
}

// round 6
// speedup vs baseline: 1.5000x; 1.1493x over previous
#include <cuda_runtime.h>
#include <math.h>

#define NN 100000
#define NE 3200000
#define SLOPE 0.01f

// ---------------- scratch (device globals; no allocation allowed) ----------
__device__ __align__(16) int   g_cnt   [NN];
__device__ __align__(16) int   g_rowptr[NN + 1];
__device__ __align__(16) int   g_next  [NN];
__device__ __align__(16) int   g_bsum  [32];
__device__ __align__(16) int   g_csr   [NE];
__device__ __align__(16) float g_dinv  [NN];
__device__ __align__(16) float g_h     [NN*16];
__device__ __align__(16) float g_xw    [NN*16];
__device__ float g_W[2*256];
__device__ int   g_is64;

__device__ __forceinline__ float lrelu(float v){ return v > 0.f ? v : SLOPE*v; }
__device__ __forceinline__ int   clampi(int v){ return v < 0 ? 0 : (v >= NN ? NN-1 : v); }

// packed fp32x2 helpers (Blackwell)
__device__ __forceinline__ unsigned long long pk2(float a, float b){
    unsigned long long r;
    asm("mov.b64 %0, {%1, %2};" : "=l"(r) : "f"(a), "f"(b));
    return r;
}
__device__ __forceinline__ unsigned long long fma2(unsigned long long a,
                                                   unsigned long long b,
                                                   unsigned long long c){
    unsigned long long d;
    asm("fma.rn.f32x2 %0, %1, %2, %3;" : "=l"(d) : "l"(a), "l"(b), "l"(c));
    return d;
}
__device__ __forceinline__ float2 upk2(unsigned long long v){
    float2 r;
    asm("mov.b64 {%0, %1}, %2;" : "=f"(r.x), "=f"(r.y) : "l"(v));
    return r;
}

// ---------------- dtype detect -----------------------------------------------
__global__ void k_detect(const int* __restrict__ ei32){
    __shared__ int any;
    if (threadIdx.x == 0) any = 0;
    __syncthreads();
    int e = threadIdx.x;
    int v = ei32[2*e + 1] | ei32[2*(e + 1024) + 1] | ei32[2*(e + 2048) + 1];
    if (v) atomicOr(&any, 1);
    __syncthreads();
    if (threadIdx.x == 0) g_is64 = (any == 0) ? 1 : 0;
}

// ---------------- hypernetwork ------------------------------------------------
__global__ void k_hyper(const float* __restrict__ bih, const float* __restrict__ bhh,
                        const float* __restrict__ wtW, const float* __restrict__ wtb){
    int t = threadIdx.x;
    int l = t >> 8, j = t & 255;
    float mem[16];
#pragma unroll
    for (int m = 0; m < 16; m++){
        float r = 1.f/(1.f + expf(-(bih[l*48 + m]      + bhh[l*48 + m])));
        float z = 1.f/(1.f + expf(-(bih[l*48 + 16 + m] + bhh[l*48 + 16 + m])));
        float n = tanhf(bih[l*48 + 32 + m] + r*bhh[l*48 + 32 + m]);
        mem[m] = (1.f - z) * n;
    }
    float acc = wtb[l*256 + j];
#pragma unroll
    for (int m = 0; m < 16; m++) acc += wtW[(l*256 + j)*16 + m] * mem[m];
    g_W[l*256 + j] = acc;
}

// ---------------- degree count (dst row only) ----------------------------------
__global__ void k_cnt0(){
    int i = blockIdx.x*blockDim.x + threadIdx.x;
    if (i < NN) g_cnt[i] = 0;
}
__global__ void k_edges(const int* __restrict__ ei32){
    int p = blockIdx.x*blockDim.x + threadIdx.x;
    if (p >= NE/2) return;
    int d0, d1;
    if (g_is64){
        const longlong2* v = (const longlong2*)ei32;
        longlong2 dv = v[(NE >> 1) + p];
        d0 = (int)dv.x; d1 = (int)dv.y;
    } else {
        const int2* v = (const int2*)ei32;
        int2 dv = v[(NE >> 1) + p];
        d0 = dv.x; d1 = dv.y;
    }
    atomicAdd(&g_cnt[clampi(d0)], 1);
    atomicAdd(&g_cnt[clampi(d1)], 1);
}
__global__ void k_dinv(){
    int i = blockIdx.x*blockDim.x + threadIdx.x;
    if (i < NN) g_dinv[i] = rsqrtf((float)g_cnt[i] + 1.0f);
}

// ---------------- exclusive scan over g_cnt -> g_rowptr --------------------------
__global__ void k_scan1(){
    __shared__ int ts[512];
    int b = blockIdx.x, t = threadIdx.x;
    int base = b*4096 + t*8;
    int v[8]; int s = 0;
#pragma unroll
    for (int k = 0; k < 8; k++){
        v[k] = (base + k < NN) ? g_cnt[base + k] : 0;
        s += v[k];
    }
    ts[t] = s; __syncthreads();
#pragma unroll
    for (int off = 1; off < 512; off <<= 1){
        int y = (t >= off) ? ts[t - off] : 0;
        __syncthreads();
        ts[t] += y;
        __syncthreads();
    }
    if (t == 511) g_bsum[b] = ts[511];
    int run = ts[t] - s;
#pragma unroll
    for (int k = 0; k < 8; k++){
        if (base + k < NN) g_rowptr[base + k] = run;
        run += v[k];
    }
}
__global__ void k_scan2(int nb){
    if (threadIdx.x == 0){
        int run = 0;
        for (int i = 0; i < nb; i++){ int v = g_bsum[i]; g_bsum[i] = run; run += v; }
    }
}
__global__ void k_scan3(){
    int i = blockIdx.x*blockDim.x + threadIdx.x;
    if (i < NN){
        int r = g_rowptr[i] + g_bsum[i >> 12];
        g_rowptr[i] = r;
        g_next[i]   = r;
    }
    if (i == 0) g_rowptr[NN] = NE;
}

// ---------------- CSR fill (re-decode edge_index) --------------------------------
__global__ void k_fill(const int* __restrict__ ei32){
    int e = blockIdx.x*blockDim.x + threadIdx.x;
    if (e >= NE) return;
    int s, d;
    if (g_is64){
        s = ei32[2*(size_t)e];
        d = ei32[2*((size_t)NE + e)];
    } else {
        s = ei32[e];
        d = ei32[NE + e];
    }
    s = clampi(s); d = clampi(d);
    int pos = atomicAdd(&g_next[d], 1);
    if (pos >= 0 && pos < NE) g_csr[pos] = s;
}

// ---------------- fused preprocess MLP: 128 -> 256 -> 16 (16 nodes/batch) --------
#define P_W1 0         // 32768 floats: blocked w1v[j*256+r] = W1[r][4j..4j+3]
#define P_B1 32768     // 256
#define P_W2 33024     // 256*17 padded transpose
#define P_B2 37376     // 16
#define P_X  37392     // 2048 floats = 1024 float2 (8 node-pairs x 128 k)
#define P_H1 39440     // 16*256
#define P_R  43536     // 16*256
#define PRE_SMEM_FLOATS 47632
#define PRE_SMEM_BYTES  (PRE_SMEM_FLOATS*4)

__global__ void __launch_bounds__(512, 1)
k_pre(const float* __restrict__ x,
      const float* __restrict__ p1W, const float* __restrict__ p1b,
      const float* __restrict__ p2W, const float* __restrict__ p2b){
    extern __shared__ float sm[];
    int t = threadIdx.x;
    int g  = t >> 8;        // half 0/1 : pairs 4g..4g+3 (8 nodes)
    int tt = t & 255;       // layer-1 output index

    {
        float4* w1v = (float4*)(sm + P_W1);
        const float4* p1W4 = (const float4*)p1W;
        for (int i = t; i < 8192; i += 512){
            int j = i >> 8, r = i & 255;
            w1v[i] = p1W4[r*32 + j];
        }
        for (int i = t; i < 256; i += 512) sm[P_B1 + i] = p1b[i];
        for (int i = t; i < 4096; i += 512){
            int k = i >> 4, o = i & 15;
            sm[P_W2 + k*17 + o] = p2W[o*256 + k];
        }
        if (t < 16) sm[P_B2 + t] = p2b[t];
    }
    __syncthreads();

    const float4*     wv  = (const float4*)(sm + P_W1);
    const ulonglong2* xq  = (const ulonglong2*)(sm + P_X);
    float2*           sxp = (float2*)(sm + P_X);
    float*            hb  = sm + P_H1;
    float*            sr  = sm + P_R;
    float bb = sm[P_B1 + tt];

    // NN % 16 == 0, so every batch is full
    for (int base = blockIdx.x*16; base < NN; base += gridDim.x*16){
        // stage 16 nodes as 8 (even,odd) pairs: sxp[p*128+k]
#pragma unroll
        for (int r = 0; r < 2; r++){
            int e = t + 512*r;
            int p = e >> 7, k = e & 127;
            sxp[p*128 + k] = make_float2(x[(size_t)(base + 2*p    )*128 + k],
                                         x[(size_t)(base + 2*p + 1)*128 + k]);
        }
        __syncthreads();

        // layer 1: 4 node-pairs (8 nodes) per thread, packed f32x2 FMA
        unsigned long long acc0, acc1, acc2, acc3;
        acc0 = acc1 = acc2 = acc3 = pk2(bb, bb);
        int pbase = 4*g;
#pragma unroll 4
        for (int j = 0; j < 32; j++){
            float4 w = wv[j*256 + tt];
            unsigned long long w0 = pk2(w.x, w.x), w1 = pk2(w.y, w.y);
            unsigned long long w2 = pk2(w.z, w.z), w3 = pk2(w.w, w.w);
            ulonglong2 u0a = xq[(pbase+0)*64 + 2*j], u0b = xq[(pbase+0)*64 + 2*j + 1];
            ulonglong2 u1a = xq[(pbase+1)*64 + 2*j], u1b = xq[(pbase+1)*64 + 2*j + 1];
            ulonglong2 u2a = xq[(pbase+2)*64 + 2*j], u2b = xq[(pbase+2)*64 + 2*j + 1];
            ulonglong2 u3a = xq[(pbase+3)*64 + 2*j], u3b = xq[(pbase+3)*64 + 2*j + 1];
            acc0 = fma2(w0, u0a.x, acc0); acc0 = fma2(w1, u0a.y, acc0);
            acc0 = fma2(w2, u0b.x, acc0); acc0 = fma2(w3, u0b.y, acc0);
            acc1 = fma2(w0, u1a.x, acc1); acc1 = fma2(w1, u1a.y, acc1);
            acc1 = fma2(w2, u1b.x, acc1); acc1 = fma2(w3, u1b.y, acc1);
            acc2 = fma2(w0, u2a.x, acc2); acc2 = fma2(w1, u2a.y, acc2);
            acc2 = fma2(w2, u2b.x, acc2); acc2 = fma2(w3, u2b.y, acc2);
            acc3 = fma2(w0, u3a.x, acc3); acc3 = fma2(w1, u3a.y, acc3);
            acc3 = fma2(w2, u3b.x, acc3); acc3 = fma2(w3, u3b.y, acc3);
        }
        {
            float2 y0 = upk2(acc0), y1 = upk2(acc1), y2 = upk2(acc2), y3 = upk2(acc3);
            hb[(g*8 + 0)*256 + tt] = lrelu(y0.x);
            hb[(g*8 + 1)*256 + tt] = lrelu(y0.y);
            hb[(g*8 + 2)*256 + tt] = lrelu(y1.x);
            hb[(g*8 + 3)*256 + tt] = lrelu(y1.y);
            hb[(g*8 + 4)*256 + tt] = lrelu(y2.x);
            hb[(g*8 + 5)*256 + tt] = lrelu(y2.y);
            hb[(g*8 + 6)*256 + tt] = lrelu(y3.x);
            hb[(g*8 + 7)*256 + tt] = lrelu(y3.y);
        }
        __syncthreads();

        // layer 2 partials: 8 nodes per thread (its half)
        {
            int o = tt & 15, part = tt >> 4;
            float p[8] = {0.f,0.f,0.f,0.f,0.f,0.f,0.f,0.f};
#pragma unroll
            for (int kk = 0; kk < 16; kk++){
                int k = part*16 + kk;
                float w2s = sm[P_W2 + k*17 + o];
#pragma unroll
                for (int q = 0; q < 8; q++)
                    p[q] += hb[(g*8 + q)*256 + k]*w2s;
            }
#pragma unroll
            for (int q = 0; q < 8; q++)
                sr[(g*8 + q)*256 + part*16 + o] = p[q];
        }
        __syncthreads();

        if (t < 256){
            int n = t >> 4, o = t & 15;
            float s = 0.f;
#pragma unroll
            for (int p = 0; p < 16; p++) s += sr[n*256 + p*16 + o];
            g_h[(size_t)(base + n)*16 + o] = lrelu(s + sm[P_B2 + o]);
        }
        __syncthreads();
    }
}

// ---------------- per-layer: xw' = (h@W.T) * dinv ---------------------------------
__global__ void k_xw(int l){
    __shared__ float Ws[256];
    if (threadIdx.x < 256) Ws[threadIdx.x] = g_W[l*256 + threadIdx.x];
    __syncthreads();
    int n = blockIdx.x*blockDim.x + threadIdx.x;
    if (n >= NN) return;
    const float4* h4 = (const float4*)g_h;
    float4 a = h4[n*4+0], b = h4[n*4+1], c = h4[n*4+2], d = h4[n*4+3];
    float hv[16] = {a.x,a.y,a.z,a.w, b.x,b.y,b.z,b.w,
                    c.x,c.y,c.z,c.w, d.x,d.y,d.z,d.w};
    float di = g_dinv[n];
    float4* xw4 = (float4*)g_xw;
#pragma unroll
    for (int q = 0; q < 4; q++){
        float4 v;
        float* vp = (float*)&v;
#pragma unroll
        for (int r = 0; r < 4; r++){
            int o = q*4 + r;
            float acc = 0.f;
#pragma unroll
            for (int i = 0; i < 16; i++) acc += hv[i]*Ws[o*16 + i];
            vp[r] = acc * di;
        }
        xw4[n*4 + q] = v;
    }
}

// ---------------- gather layer 0: h[d] = lrelu(dinv*(sum+self)+b) ------------------
__global__ void __launch_bounds__(256)
k_gather(const float* __restrict__ gcnb, int l){
    int warp = (blockIdx.x*blockDim.x + threadIdx.x) >> 5;
    int lane = threadIdx.x & 31;
    if (warp >= NN) return;
    int node = warp;
    int slot = lane >> 2;
    int cg   = lane & 3;
    int beg = g_rowptr[node], end = g_rowptr[node + 1];
    const float4* xw4 = (const float4*)g_xw;

    float4 acc;
    if (slot == 0) acc = xw4[(size_t)node*4 + cg];
    else           acc = make_float4(0.f, 0.f, 0.f, 0.f);

    for (int j = beg + slot; j < end; j += 8){
        int s = g_csr[j];
        float4 v = xw4[(size_t)s*4 + cg];
        acc.x += v.x; acc.y += v.y; acc.z += v.z; acc.w += v.w;
    }
#pragma unroll
    for (int off = 4; off < 32; off <<= 1){
        acc.x += __shfl_xor_sync(0xffffffff, acc.x, off);
        acc.y += __shfl_xor_sync(0xffffffff, acc.y, off);
        acc.z += __shfl_xor_sync(0xffffffff, acc.z, off);
        acc.w += __shfl_xor_sync(0xffffffff, acc.w, off);
    }
    if (lane < 4){
        float di = g_dinv[node];
        const float* bp = gcnb + l*16 + cg*4;
        float4 r;
        r.x = lrelu(di*acc.x + bp[0]);
        r.y = lrelu(di*acc.y + bp[1]);
        r.z = lrelu(di*acc.z + bp[2]);
        r.w = lrelu(di*acc.w + bp[3]);
        ((float4*)g_h)[(size_t)node*4 + cg] = r;
    }
}

// ---------------- gather layer 1 + fused post heads ---------------------------------
__global__ void __launch_bounds__(256)
k_gather2(const float* __restrict__ gcnb,
          const float* __restrict__ po1W, const float* __restrict__ po1b,
          const float* __restrict__ poaW, const float* __restrict__ poab,
          float* __restrict__ out, int out_size){
    int warp = (blockIdx.x*blockDim.x + threadIdx.x) >> 5;
    int lane = threadIdx.x & 31;
    if (warp >= NN) return;
    int node = warp;
    int slot = lane >> 2;
    int cg   = lane & 3;
    int beg = g_rowptr[node], end = g_rowptr[node + 1];
    const float4* xw4 = (const float4*)g_xw;

    float4 acc;
    if (slot == 0) acc = xw4[(size_t)node*4 + cg];
    else           acc = make_float4(0.f, 0.f, 0.f, 0.f);

    for (int j = beg + slot; j < end; j += 8){
        int s = g_csr[j];
        float4 v = xw4[(size_t)s*4 + cg];
        acc.x += v.x; acc.y += v.y; acc.z += v.z; acc.w += v.w;
    }
#pragma unroll
    for (int off = 4; off < 32; off <<= 1){
        acc.x += __shfl_xor_sync(0xffffffff, acc.x, off);
        acc.y += __shfl_xor_sync(0xffffffff, acc.y, off);
        acc.z += __shfl_xor_sync(0xffffffff, acc.z, off);
        acc.w += __shfl_xor_sync(0xffffffff, acc.w, off);
    }
    if (lane < 4){
        float di = g_dinv[node];
        const float* bp = gcnb + 16 + cg*4;   // l = 1
        float4 r;
        r.x = lrelu(di*acc.x + bp[0]);
        r.y = lrelu(di*acc.y + bp[1]);
        r.z = lrelu(di*acc.z + bp[2]);
        r.w = lrelu(di*acc.w + bp[3]);
        if (out_size >= 18*NN)
            ((float4*)(out + 2*NN))[(size_t)node*4 + cg] = r;
        // heads: partial dot per quad lane
        int c0 = cg*4;
        float sp = r.x*(po1W[c0+0] + po1W[16+c0+0])
                 + r.y*(po1W[c0+1] + po1W[16+c0+1])
                 + r.z*(po1W[c0+2] + po1W[16+c0+2])
                 + r.w*(po1W[c0+3] + po1W[16+c0+3]);
        float ap = r.x*poaW[c0+0] + r.y*poaW[c0+1]
                 + r.z*poaW[c0+2] + r.w*poaW[c0+3];
        unsigned qm = 0xFu << ((lane >> 2) << 2);
        sp += __shfl_xor_sync(qm, sp, 1); sp += __shfl_xor_sync(qm, sp, 2);
        ap += __shfl_xor_sync(qm, ap, 1); ap += __shfl_xor_sync(qm, ap, 2);
        if (cg == 0){
            out[node] = sp + po1b[0] + po1b[1];
            if (out_size >= 2*NN) out[NN + node] = ap + poab[0];
        }
    }
}

// ---------------- launch --------------------------------------------------------------
extern "C" void kernel_launch(void* const* d_in, const int* in_sizes, int n_in,
                              void* d_out, int out_size){
    const float* x    = (const float*)d_in[0];
    const int*   ei32 = (const int*)d_in[1];
    const float* p1W  = (const float*)d_in[2];
    const float* p1b  = (const float*)d_in[3];
    const float* p2W  = (const float*)d_in[4];
    const float* p2b  = (const float*)d_in[5];
    const float* bih  = (const float*)d_in[6];
    const float* bhh  = (const float*)d_in[7];
    const float* wtW  = (const float*)d_in[8];
    const float* wtb  = (const float*)d_in[9];
    const float* gcnb = (const float*)d_in[10];
    const float* po1W = (const float*)d_in[11];
    const float* po1b = (const float*)d_in[12];
    const float* poaW = (const float*)d_in[13];
    const float* poab = (const float*)d_in[14];
    float* out = (float*)d_out;

    cudaFuncSetAttribute(k_pre, cudaFuncAttributeMaxDynamicSharedMemorySize,
                         PRE_SMEM_BYTES);

    const int NB_N = (NN + 255)/256;
    const int NB_E = (NE + 255)/256;
    const int NB_E2 = (NE/2 + 255)/256;
    const int NB_SCAN = (NN + 4095)/4096;   // 25
    const int NB_G = (NN*32 + 255)/256;     // warp per node

    k_detect<<<1, 1024>>>(ei32);
    k_hyper <<<1, 512>>>(bih, bhh, wtW, wtb);
    k_cnt0  <<<NB_N, 256>>>();
    k_edges <<<NB_E2, 256>>>(ei32);
    k_dinv  <<<NB_N, 256>>>();
    k_scan1 <<<NB_SCAN, 512>>>();
    k_scan2 <<<1, 32>>>(NB_SCAN);
    k_scan3 <<<NB_N, 256>>>();
    k_fill  <<<NB_E, 256>>>(ei32);
    k_pre   <<<148, 512, PRE_SMEM_BYTES>>>(x, p1W, p1b, p2W, p2b);

    k_xw     <<<NB_N, 256>>>(0);
    k_gather <<<NB_G, 256>>>(gcnb, 0);
    k_xw     <<<NB_N, 256>>>(1);
    k_gather2<<<NB_G, 256>>>(gcnb, po1W, po1b, poaW, poab, out, out_size);
}

// round 7
// speedup vs baseline: 1.5090x; 1.0060x over previous
#include <cuda_runtime.h>
#include <math.h>

#define NN 100000
#define NE 3200000
#define SLOPE 0.01f

// ---------------- scratch (device globals; no allocation allowed) ----------
__device__ __align__(16) int   g_cnt   [NN];
__device__ __align__(16) int   g_rowptr[NN + 1];
__device__ __align__(16) int   g_next  [NN];
__device__ __align__(16) int   g_bsum  [32];
__device__ __align__(16) int   g_csr   [NE];
__device__ __align__(16) float g_dinv  [NN];
__device__ __align__(16) float g_h     [NN*16];
__device__ __align__(16) float g_xw    [NN*16];
__device__ float g_W[2*256];
__device__ int   g_is64;

__device__ __forceinline__ float lrelu(float v){ return v > 0.f ? v : SLOPE*v; }
__device__ __forceinline__ int   clampi(int v){ return v < 0 ? 0 : (v >= NN ? NN-1 : v); }

// packed fp32x2 helpers (Blackwell)
__device__ __forceinline__ unsigned long long pk2(float a, float b){
    unsigned long long r;
    asm("mov.b64 %0, {%1, %2};" : "=l"(r) : "f"(a), "f"(b));
    return r;
}
__device__ __forceinline__ unsigned long long fma2(unsigned long long a,
                                                   unsigned long long b,
                                                   unsigned long long c){
    unsigned long long d;
    asm("fma.rn.f32x2 %0, %1, %2, %3;" : "=l"(d) : "l"(a), "l"(b), "l"(c));
    return d;
}
__device__ __forceinline__ float2 upk2(unsigned long long v){
    float2 r;
    asm("mov.b64 {%0, %1}, %2;" : "=f"(r.x), "=f"(r.y) : "l"(v));
    return r;
}

// ---------------- fused init: block0=dtype detect, block1=hyper, rest=cnt0 ----
__global__ void __launch_bounds__(512)
k_init(const int* __restrict__ ei32,
       const float* __restrict__ bih, const float* __restrict__ bhh,
       const float* __restrict__ wtW, const float* __restrict__ wtb){
    int b = blockIdx.x;
    if (b == 0){
        __shared__ int any;
        if (threadIdx.x == 0) any = 0;
        __syncthreads();
        int v = 0;
#pragma unroll
        for (int q = 0; q < 6; q++){
            int e = threadIdx.x + 512*q;
            v |= ei32[2*e + 1];
        }
        if (v) atomicOr(&any, 1);
        __syncthreads();
        if (threadIdx.x == 0) g_is64 = (any == 0) ? 1 : 0;
    } else if (b == 1){
        int t = threadIdx.x;
        int l = t >> 8, j = t & 255;
        float mem[16];
#pragma unroll
        for (int m = 0; m < 16; m++){
            float r = 1.f/(1.f + expf(-(bih[l*48 + m]      + bhh[l*48 + m])));
            float z = 1.f/(1.f + expf(-(bih[l*48 + 16 + m] + bhh[l*48 + 16 + m])));
            float n = tanhf(bih[l*48 + 32 + m] + r*bhh[l*48 + 32 + m]);
            mem[m] = (1.f - z) * n;
        }
        float acc = wtb[l*256 + j];
#pragma unroll
        for (int m = 0; m < 16; m++) acc += wtW[(l*256 + j)*16 + m] * mem[m];
        g_W[l*256 + j] = acc;
    } else {
        int i = (b - 2)*512 + threadIdx.x;
        if (i < NN) g_cnt[i] = 0;
    }
}

// ---------------- degree count (dst row only) ----------------------------------
__global__ void k_edges(const int* __restrict__ ei32){
    int p = blockIdx.x*blockDim.x + threadIdx.x;
    if (p >= NE/2) return;
    int d0, d1;
    if (g_is64){
        const longlong2* v = (const longlong2*)ei32;
        longlong2 dv = v[(NE >> 1) + p];
        d0 = (int)dv.x; d1 = (int)dv.y;
    } else {
        const int2* v = (const int2*)ei32;
        int2 dv = v[(NE >> 1) + p];
        d0 = dv.x; d1 = dv.y;
    }
    atomicAdd(&g_cnt[clampi(d0)], 1);
    atomicAdd(&g_cnt[clampi(d1)], 1);
}

// ---------------- exclusive scan over g_cnt -> g_rowptr (+ dinv fused) -----------
__global__ void k_scan1(){
    __shared__ int ts[512];
    int b = blockIdx.x, t = threadIdx.x;
    int base = b*4096 + t*8;
    int v[8]; int s = 0;
#pragma unroll
    for (int k = 0; k < 8; k++){
        v[k] = (base + k < NN) ? g_cnt[base + k] : 0;
        s += v[k];
        if (base + k < NN) g_dinv[base + k] = rsqrtf((float)v[k] + 1.0f);
    }
    ts[t] = s; __syncthreads();
#pragma unroll
    for (int off = 1; off < 512; off <<= 1){
        int y = (t >= off) ? ts[t - off] : 0;
        __syncthreads();
        ts[t] += y;
        __syncthreads();
    }
    if (t == 511) g_bsum[b] = ts[511];
    int run = ts[t] - s;
#pragma unroll
    for (int k = 0; k < 8; k++){
        if (base + k < NN) g_rowptr[base + k] = run;
        run += v[k];
    }
}
__global__ void k_scan2(int nb){
    if (threadIdx.x == 0){
        int run = 0;
        for (int i = 0; i < nb; i++){ int v = g_bsum[i]; g_bsum[i] = run; run += v; }
    }
}
__global__ void k_scan3(){
    int i = blockIdx.x*blockDim.x + threadIdx.x;
    if (i < NN){
        int r = g_rowptr[i] + g_bsum[i >> 12];
        g_rowptr[i] = r;
        g_next[i]   = r;
    }
    if (i == 0) g_rowptr[NN] = NE;
}

// ---------------- CSR fill (re-decode edge_index) --------------------------------
__global__ void k_fill(const int* __restrict__ ei32){
    int e = blockIdx.x*blockDim.x + threadIdx.x;
    if (e >= NE) return;
    int s, d;
    if (g_is64){
        s = ei32[2*(size_t)e];
        d = ei32[2*((size_t)NE + e)];
    } else {
        s = ei32[e];
        d = ei32[NE + e];
    }
    s = clampi(s); d = clampi(d);
    int pos = atomicAdd(&g_next[d], 1);
    if (pos >= 0 && pos < NE) g_csr[pos] = s;
}

// ---------------- fused preprocess MLP: 128 -> 256 -> 16 (16 nodes/batch) --------
#define P_W1 0         // 32768 floats: blocked w1v[j*256+r] = W1[r][4j..4j+3]
#define P_B1 32768     // 256
#define P_W2 33024     // 256*17 padded transpose
#define P_B2 37376     // 16
#define P_X  37392     // 2048 floats = 1024 float2 (8 node-pairs x 128 k)
#define P_H1 39440     // 16*256
#define P_R  43536     // 16*256
#define PRE_SMEM_FLOATS 47632
#define PRE_SMEM_BYTES  (PRE_SMEM_FLOATS*4)

__global__ void __launch_bounds__(512, 1)
k_pre(const float* __restrict__ x,
      const float* __restrict__ p1W, const float* __restrict__ p1b,
      const float* __restrict__ p2W, const float* __restrict__ p2b){
    extern __shared__ float sm[];
    int t = threadIdx.x;
    int g  = t >> 8;        // half 0/1 : pairs 4g..4g+3 (8 nodes)
    int tt = t & 255;       // layer-1 output index

    {
        float4* w1v = (float4*)(sm + P_W1);
        const float4* p1W4 = (const float4*)p1W;
        for (int i = t; i < 8192; i += 512){
            int j = i >> 8, r = i & 255;
            w1v[i] = p1W4[r*32 + j];
        }
        for (int i = t; i < 256; i += 512) sm[P_B1 + i] = p1b[i];
        for (int i = t; i < 4096; i += 512){
            int k = i >> 4, o = i & 15;
            sm[P_W2 + k*17 + o] = p2W[o*256 + k];
        }
        if (t < 16) sm[P_B2 + t] = p2b[t];
    }
    __syncthreads();

    const float4*     wv  = (const float4*)(sm + P_W1);
    const ulonglong2* xq  = (const ulonglong2*)(sm + P_X);
    float2*           sxp = (float2*)(sm + P_X);
    float*            hb  = sm + P_H1;
    float*            sr  = sm + P_R;
    float bb = sm[P_B1 + tt];

    // NN % 16 == 0, so every batch is full
    for (int base = blockIdx.x*16; base < NN; base += gridDim.x*16){
        // stage 16 nodes as 8 (even,odd) pairs: sxp[p*128+k]
#pragma unroll
        for (int r = 0; r < 2; r++){
            int e = t + 512*r;
            int p = e >> 7, k = e & 127;
            sxp[p*128 + k] = make_float2(x[(size_t)(base + 2*p    )*128 + k],
                                         x[(size_t)(base + 2*p + 1)*128 + k]);
        }
        __syncthreads();

        // layer 1: 4 node-pairs (8 nodes) per thread, packed f32x2 FMA
        unsigned long long acc0, acc1, acc2, acc3;
        acc0 = acc1 = acc2 = acc3 = pk2(bb, bb);
        int pbase = 4*g;
#pragma unroll 4
        for (int j = 0; j < 32; j++){
            float4 w = wv[j*256 + tt];
            unsigned long long w0 = pk2(w.x, w.x), w1 = pk2(w.y, w.y);
            unsigned long long w2 = pk2(w.z, w.z), w3 = pk2(w.w, w.w);
            ulonglong2 u0a = xq[(pbase+0)*64 + 2*j], u0b = xq[(pbase+0)*64 + 2*j + 1];
            ulonglong2 u1a = xq[(pbase+1)*64 + 2*j], u1b = xq[(pbase+1)*64 + 2*j + 1];
            ulonglong2 u2a = xq[(pbase+2)*64 + 2*j], u2b = xq[(pbase+2)*64 + 2*j + 1];
            ulonglong2 u3a = xq[(pbase+3)*64 + 2*j], u3b = xq[(pbase+3)*64 + 2*j + 1];
            acc0 = fma2(w0, u0a.x, acc0); acc0 = fma2(w1, u0a.y, acc0);
            acc0 = fma2(w2, u0b.x, acc0); acc0 = fma2(w3, u0b.y, acc0);
            acc1 = fma2(w0, u1a.x, acc1); acc1 = fma2(w1, u1a.y, acc1);
            acc1 = fma2(w2, u1b.x, acc1); acc1 = fma2(w3, u1b.y, acc1);
            acc2 = fma2(w0, u2a.x, acc2); acc2 = fma2(w1, u2a.y, acc2);
            acc2 = fma2(w2, u2b.x, acc2); acc2 = fma2(w3, u2b.y, acc2);
            acc3 = fma2(w0, u3a.x, acc3); acc3 = fma2(w1, u3a.y, acc3);
            acc3 = fma2(w2, u3b.x, acc3); acc3 = fma2(w3, u3b.y, acc3);
        }
        {
            float2 y0 = upk2(acc0), y1 = upk2(acc1), y2 = upk2(acc2), y3 = upk2(acc3);
            hb[(g*8 + 0)*256 + tt] = lrelu(y0.x);
            hb[(g*8 + 1)*256 + tt] = lrelu(y0.y);
            hb[(g*8 + 2)*256 + tt] = lrelu(y1.x);
            hb[(g*8 + 3)*256 + tt] = lrelu(y1.y);
            hb[(g*8 + 4)*256 + tt] = lrelu(y2.x);
            hb[(g*8 + 5)*256 + tt] = lrelu(y2.y);
            hb[(g*8 + 6)*256 + tt] = lrelu(y3.x);
            hb[(g*8 + 7)*256 + tt] = lrelu(y3.y);
        }
        __syncthreads();

        // layer 2 partials: 8 nodes per thread (its half)
        {
            int o = tt & 15, part = tt >> 4;
            float p[8] = {0.f,0.f,0.f,0.f,0.f,0.f,0.f,0.f};
#pragma unroll
            for (int kk = 0; kk < 16; kk++){
                int k = part*16 + kk;
                float w2s = sm[P_W2 + k*17 + o];
#pragma unroll
                for (int q = 0; q < 8; q++)
                    p[q] += hb[(g*8 + q)*256 + k]*w2s;
            }
#pragma unroll
            for (int q = 0; q < 8; q++)
                sr[(g*8 + q)*256 + part*16 + o] = p[q];
        }
        __syncthreads();

        if (t < 256){
            int n = t >> 4, o = t & 15;
            float s = 0.f;
#pragma unroll
            for (int p = 0; p < 16; p++) s += sr[n*256 + p*16 + o];
            g_h[(size_t)(base + n)*16 + o] = lrelu(s + sm[P_B2 + o]);
        }
        __syncthreads();
    }
}

// ---------------- per-layer: xw' = (h@W.T) * dinv ---------------------------------
__global__ void k_xw(int l){
    __shared__ float Ws[256];
    if (threadIdx.x < 256) Ws[threadIdx.x] = g_W[l*256 + threadIdx.x];
    __syncthreads();
    int n = blockIdx.x*blockDim.x + threadIdx.x;
    if (n >= NN) return;
    const float4* h4 = (const float4*)g_h;
    float4 a = h4[n*4+0], b = h4[n*4+1], c = h4[n*4+2], d = h4[n*4+3];
    float hv[16] = {a.x,a.y,a.z,a.w, b.x,b.y,b.z,b.w,
                    c.x,c.y,c.z,c.w, d.x,d.y,d.z,d.w};
    float di = g_dinv[n];
    float4* xw4 = (float4*)g_xw;
#pragma unroll
    for (int q = 0; q < 4; q++){
        float4 v;
        float* vp = (float*)&v;
#pragma unroll
        for (int r = 0; r < 4; r++){
            int o = q*4 + r;
            float acc = 0.f;
#pragma unroll
            for (int i = 0; i < 16; i++) acc += hv[i]*Ws[o*16 + i];
            vp[r] = acc * di;
        }
        xw4[n*4 + q] = v;
    }
}

// ---------------- gather layer 0: h[d] = lrelu(dinv*(sum+self)+b) ------------------
__global__ void __launch_bounds__(256)
k_gather(const float* __restrict__ gcnb, int l){
    int warp = (blockIdx.x*blockDim.x + threadIdx.x) >> 5;
    int lane = threadIdx.x & 31;
    if (warp >= NN) return;
    int node = warp;
    int slot = lane >> 2;
    int cg   = lane & 3;
    int beg = g_rowptr[node], end = g_rowptr[node + 1];
    const float4* xw4 = (const float4*)g_xw;

    float4 acc;
    if (slot == 0) acc = xw4[(size_t)node*4 + cg];
    else           acc = make_float4(0.f, 0.f, 0.f, 0.f);

    for (int j = beg + slot; j < end; j += 8){
        int s = g_csr[j];
        float4 v = xw4[(size_t)s*4 + cg];
        acc.x += v.x; acc.y += v.y; acc.z += v.z; acc.w += v.w;
    }
#pragma unroll
    for (int off = 4; off < 32; off <<= 1){
        acc.x += __shfl_xor_sync(0xffffffff, acc.x, off);
        acc.y += __shfl_xor_sync(0xffffffff, acc.y, off);
        acc.z += __shfl_xor_sync(0xffffffff, acc.z, off);
        acc.w += __shfl_xor_sync(0xffffffff, acc.w, off);
    }
    if (lane < 4){
        float di = g_dinv[node];
        const float* bp = gcnb + l*16 + cg*4;
        float4 r;
        r.x = lrelu(di*acc.x + bp[0]);
        r.y = lrelu(di*acc.y + bp[1]);
        r.z = lrelu(di*acc.z + bp[2]);
        r.w = lrelu(di*acc.w + bp[3]);
        ((float4*)g_h)[(size_t)node*4 + cg] = r;
    }
}

// ---------------- gather layer 1 + fused post heads ---------------------------------
__global__ void __launch_bounds__(256)
k_gather2(const float* __restrict__ gcnb,
          const float* __restrict__ po1W, const float* __restrict__ po1b,
          const float* __restrict__ poaW, const float* __restrict__ poab,
          float* __restrict__ out, int out_size){
    int warp = (blockIdx.x*blockDim.x + threadIdx.x) >> 5;
    int lane = threadIdx.x & 31;
    if (warp >= NN) return;
    int node = warp;
    int slot = lane >> 2;
    int cg   = lane & 3;
    int beg = g_rowptr[node], end = g_rowptr[node + 1];
    const float4* xw4 = (const float4*)g_xw;

    float4 acc;
    if (slot == 0) acc = xw4[(size_t)node*4 + cg];
    else           acc = make_float4(0.f, 0.f, 0.f, 0.f);

    for (int j = beg + slot; j < end; j += 8){
        int s = g_csr[j];
        float4 v = xw4[(size_t)s*4 + cg];
        acc.x += v.x; acc.y += v.y; acc.z += v.z; acc.w += v.w;
    }
#pragma unroll
    for (int off = 4; off < 32; off <<= 1){
        acc.x += __shfl_xor_sync(0xffffffff, acc.x, off);
        acc.y += __shfl_xor_sync(0xffffffff, acc.y, off);
        acc.z += __shfl_xor_sync(0xffffffff, acc.z, off);
        acc.w += __shfl_xor_sync(0xffffffff, acc.w, off);
    }
    if (lane < 4){
        float di = g_dinv[node];
        const float* bp = gcnb + 16 + cg*4;   // l = 1
        float4 r;
        r.x = lrelu(di*acc.x + bp[0]);
        r.y = lrelu(di*acc.y + bp[1]);
        r.z = lrelu(di*acc.z + bp[2]);
        r.w = lrelu(di*acc.w + bp[3]);
        if (out_size >= 18*NN)
            ((float4*)(out + 2*NN))[(size_t)node*4 + cg] = r;
        int c0 = cg*4;
        float sp = r.x*(po1W[c0+0] + po1W[16+c0+0])
                 + r.y*(po1W[c0+1] + po1W[16+c0+1])
                 + r.z*(po1W[c0+2] + po1W[16+c0+2])
                 + r.w*(po1W[c0+3] + po1W[16+c0+3]);
        float ap = r.x*poaW[c0+0] + r.y*poaW[c0+1]
                 + r.z*poaW[c0+2] + r.w*poaW[c0+3];
        unsigned qm = 0xFu << ((lane >> 2) << 2);
        sp += __shfl_xor_sync(qm, sp, 1); sp += __shfl_xor_sync(qm, sp, 2);
        ap += __shfl_xor_sync(qm, ap, 1); ap += __shfl_xor_sync(qm, ap, 2);
        if (cg == 0){
            out[node] = sp + po1b[0] + po1b[1];
            if (out_size >= 2*NN) out[NN + node] = ap + poab[0];
        }
    }
}

// ---------------- launch --------------------------------------------------------------
extern "C" void kernel_launch(void* const* d_in, const int* in_sizes, int n_in,
                              void* d_out, int out_size){
    const float* x    = (const float*)d_in[0];
    const int*   ei32 = (const int*)d_in[1];
    const float* p1W  = (const float*)d_in[2];
    const float* p1b  = (const float*)d_in[3];
    const float* p2W  = (const float*)d_in[4];
    const float* p2b  = (const float*)d_in[5];
    const float* bih  = (const float*)d_in[6];
    const float* bhh  = (const float*)d_in[7];
    const float* wtW  = (const float*)d_in[8];
    const float* wtb  = (const float*)d_in[9];
    const float* gcnb = (const float*)d_in[10];
    const float* po1W = (const float*)d_in[11];
    const float* po1b = (const float*)d_in[12];
    const float* poaW = (const float*)d_in[13];
    const float* poab = (const float*)d_in[14];
    float* out = (float*)d_out;

    cudaFuncSetAttribute(k_pre, cudaFuncAttributeMaxDynamicSharedMemorySize,
                         PRE_SMEM_BYTES);

    const int NB_N = (NN + 255)/256;
    const int NB_E = (NE + 255)/256;
    const int NB_E2 = (NE/2 + 255)/256;
    const int NB_SCAN = (NN + 4095)/4096;   // 25
    const int NB_G = (NN*32 + 255)/256;     // warp per node
    const int NB_I = 2 + (NN + 511)/512;    // init: detect + hyper + cnt0

    // launch index:        0       1        2        3 (profiled slot)
    k_init  <<<NB_I, 512>>>(ei32, bih, bhh, wtW, wtb);
    k_edges <<<NB_E2, 256>>>(ei32);
    k_scan1 <<<NB_SCAN, 512>>>();
    k_pre   <<<148, 512, PRE_SMEM_BYTES>>>(x, p1W, p1b, p2W, p2b);
    // 4..
    k_scan2 <<<1, 32>>>(NB_SCAN);
    k_scan3 <<<NB_N, 256>>>();
    k_fill  <<<NB_E, 256>>>(ei32);
    k_xw     <<<NB_N, 256>>>(0);
    k_gather <<<NB_G, 256>>>(gcnb, 0);
    k_xw     <<<NB_N, 256>>>(1);
    k_gather2<<<NB_G, 256>>>(gcnb, po1W, po1b, poaW, poab, out, out_size);
}

// round 8
// speedup vs baseline: 1.8645x; 1.2356x over previous
#include <cuda_runtime.h>
#include <math.h>

#define NN 100000
#define NE 3200000
#define SLOPE 0.01f

// ---------------- scratch (device globals; no allocation allowed) ----------
__device__ __align__(16) int   g_cnt   [NN];
__device__ __align__(16) int   g_rowptr[NN + 1];
__device__ __align__(16) int   g_next  [NN];
__device__ __align__(16) int   g_bsum  [32];
__device__ __align__(16) int   g_csr   [NE];
__device__ __align__(16) float g_dinv  [NN];
__device__ __align__(16) float g_h     [NN*16];
__device__ __align__(16) float g_xw    [NN*16];
__device__ float g_W[2*256];
__device__ int   g_is64;

__device__ __forceinline__ float lrelu(float v){ return v > 0.f ? v : SLOPE*v; }
__device__ __forceinline__ int   clampi(int v){ return v < 0 ? 0 : (v >= NN ? NN-1 : v); }

// packed fp32x2 helpers (Blackwell)
__device__ __forceinline__ unsigned long long pk2(float a, float b){
    unsigned long long r;
    asm("mov.b64 %0, {%1, %2};" : "=l"(r) : "f"(a), "f"(b));
    return r;
}
__device__ __forceinline__ unsigned long long fma2(unsigned long long a,
                                                   unsigned long long b,
                                                   unsigned long long c){
    unsigned long long d;
    asm("fma.rn.f32x2 %0, %1, %2, %3;" : "=l"(d) : "l"(a), "l"(b), "l"(c));
    return d;
}
__device__ __forceinline__ float2 upk2(unsigned long long v){
    float2 r;
    asm("mov.b64 {%0, %1}, %2;" : "=f"(r.x), "=f"(r.y) : "l"(v));
    return r;
}

// ---------------- fused init: block0=dtype detect, block1=hyper, rest=cnt0 ----
__global__ void __launch_bounds__(512)
k_init(const int* __restrict__ ei32,
       const float* __restrict__ bih, const float* __restrict__ bhh,
       const float* __restrict__ wtW, const float* __restrict__ wtb){
    int b = blockIdx.x;
    if (b == 0){
        __shared__ int any;
        if (threadIdx.x == 0) any = 0;
        __syncthreads();
        int v = 0;
#pragma unroll
        for (int q = 0; q < 6; q++){
            int e = threadIdx.x + 512*q;
            v |= ei32[2*e + 1];
        }
        if (v) atomicOr(&any, 1);
        __syncthreads();
        if (threadIdx.x == 0) g_is64 = (any == 0) ? 1 : 0;
    } else if (b == 1){
        int t = threadIdx.x;
        int l = t >> 8, j = t & 255;
        float mem[16];
#pragma unroll
        for (int m = 0; m < 16; m++){
            float r = 1.f/(1.f + expf(-(bih[l*48 + m]      + bhh[l*48 + m])));
            float z = 1.f/(1.f + expf(-(bih[l*48 + 16 + m] + bhh[l*48 + 16 + m])));
            float n = tanhf(bih[l*48 + 32 + m] + r*bhh[l*48 + 32 + m]);
            mem[m] = (1.f - z) * n;
        }
        float acc = wtb[l*256 + j];
#pragma unroll
        for (int m = 0; m < 16; m++) acc += wtW[(l*256 + j)*16 + m] * mem[m];
        g_W[l*256 + j] = acc;
    } else {
        int i = (b - 2)*512 + threadIdx.x;
        if (i < NN) g_cnt[i] = 0;
    }
}

// ---------------- degree count (dst row only) ----------------------------------
__global__ void k_edges(const int* __restrict__ ei32){
    int p = blockIdx.x*blockDim.x + threadIdx.x;
    if (p >= NE/2) return;
    int d0, d1;
    if (g_is64){
        const longlong2* v = (const longlong2*)ei32;
        longlong2 dv = v[(NE >> 1) + p];
        d0 = (int)dv.x; d1 = (int)dv.y;
    } else {
        const int2* v = (const int2*)ei32;
        int2 dv = v[(NE >> 1) + p];
        d0 = dv.x; d1 = dv.y;
    }
    atomicAdd(&g_cnt[clampi(d0)], 1);
    atomicAdd(&g_cnt[clampi(d1)], 1);
}

// ---------------- exclusive scan over g_cnt -> g_rowptr (+ dinv fused) -----------
__global__ void k_scan1(){
    __shared__ int ts[512];
    int b = blockIdx.x, t = threadIdx.x;
    int base = b*4096 + t*8;
    int v[8]; int s = 0;
#pragma unroll
    for (int k = 0; k < 8; k++){
        v[k] = (base + k < NN) ? g_cnt[base + k] : 0;
        s += v[k];
        if (base + k < NN) g_dinv[base + k] = rsqrtf((float)v[k] + 1.0f);
    }
    ts[t] = s; __syncthreads();
#pragma unroll
    for (int off = 1; off < 512; off <<= 1){
        int y = (t >= off) ? ts[t - off] : 0;
        __syncthreads();
        ts[t] += y;
        __syncthreads();
    }
    if (t == 511) g_bsum[b] = ts[511];
    int run = ts[t] - s;
#pragma unroll
    for (int k = 0; k < 8; k++){
        if (base + k < NN) g_rowptr[base + k] = run;
        run += v[k];
    }
}
__global__ void k_scan2(int nb){
    if (threadIdx.x == 0){
        int run = 0;
        for (int i = 0; i < nb; i++){ int v = g_bsum[i]; g_bsum[i] = run; run += v; }
    }
}
__global__ void k_scan3(){
    int i = blockIdx.x*blockDim.x + threadIdx.x;
    if (i < NN){
        int r = g_rowptr[i] + g_bsum[i >> 12];
        g_rowptr[i] = r;
        g_next[i]   = r;
    }
    if (i == 0) g_rowptr[NN] = NE;
}

// ---------------- CSR fill (re-decode edge_index) --------------------------------
__global__ void k_fill(const int* __restrict__ ei32){
    int e = blockIdx.x*blockDim.x + threadIdx.x;
    if (e >= NE) return;
    int s, d;
    if (g_is64){
        s = ei32[2*(size_t)e];
        d = ei32[2*((size_t)NE + e)];
    } else {
        s = ei32[e];
        d = ei32[NE + e];
    }
    s = clampi(s); d = clampi(d);
    int pos = atomicAdd(&g_next[d], 1);
    if (pos >= 0 && pos < NE) g_csr[pos] = s;
}

// ---------------- fused preprocess MLP: 128 -> 256 -> 16 -------------------------
// 32 nodes (16 even/odd pairs) per batch; T_o=2 x T_p=4 register tile (0.5 wf/FFMA2)
// smem layout (floats):
#define P_W1 0         // 32768: blocked w1v[j*256+r] = W1[r][4j..4j+3]
#define P_B1 32768     // 256
#define P_W2 33024     // 4352 = 256*17 padded transpose
#define P_B2 37376     // 16
#define P_X  37392     // 4096: 16 pairs x 128 k x float2
#define P_H1 41488     // 8192: 16 pairs x 256 o x float2  (pair-packed h1)
#define P_R  49680     // 8192: 16 pairs x 16 part x 16 o x float2
#define PRE_SMEM_FLOATS 57872
#define PRE_SMEM_BYTES  (PRE_SMEM_FLOATS*4)   // 231488 <= 232448

__global__ void __launch_bounds__(512, 1)
k_pre(const float* __restrict__ x,
      const float* __restrict__ p1W, const float* __restrict__ p1b,
      const float* __restrict__ p2W, const float* __restrict__ p2b){
    extern __shared__ float sm[];
    int t = threadIdx.x;

    // stage weights once
    {
        float4* w1v = (float4*)(sm + P_W1);
        const float4* p1W4 = (const float4*)p1W;
        for (int i = t; i < 8192; i += 512){
            int j = i >> 8, r = i & 255;
            w1v[i] = p1W4[r*32 + j];
        }
        for (int i = t; i < 256; i += 512) sm[P_B1 + i] = p1b[i];
        for (int i = t; i < 4096; i += 512){
            int k = i >> 4, o = i & 15;
            sm[P_W2 + k*17 + o] = p2W[o*256 + k];
        }
        if (t < 16) sm[P_B2 + t] = p2b[t];
    }
    __syncthreads();

    const float4*              wv  = (const float4*)(sm + P_W1);
    const ulonglong2*          xq  = (const ulonglong2*)(sm + P_X);
    float2*                    sxp = (float2*)(sm + P_X);
    float2*                    hbp = (float2*)(sm + P_H1);
    const unsigned long long*  hbu = (const unsigned long long*)(sm + P_H1);
    unsigned long long*        sru = (unsigned long long*)(sm + P_R);
    const float2*              srp = (const float2*)(sm + P_R);

    int oo = t & 127;      // output group: columns oo and oo+128
    int pg = t >> 7;       // pair group 0..3 : pairs 4pg..4pg+3
    float b0 = sm[P_B1 + oo], b1 = sm[P_B1 + 128 + oo];

    // NN % 32 == 0
    for (int base = blockIdx.x*32; base < NN; base += gridDim.x*32){
        // stage 32 nodes as 16 (even,odd) pairs: sxp[p*128+k]
#pragma unroll
        for (int r = 0; r < 4; r++){
            int e = t + 512*r;
            int p = e >> 7, k = e & 127;
            sxp[p*128 + k] = make_float2(x[(size_t)(base + 2*p    )*128 + k],
                                         x[(size_t)(base + 2*p + 1)*128 + k]);
        }
        __syncthreads();

        // layer 1: 2 outputs x 4 pairs per thread
        unsigned long long a00, a01, a02, a03, a10, a11, a12, a13;
        a00 = a01 = a02 = a03 = pk2(b0, b0);
        a10 = a11 = a12 = a13 = pk2(b1, b1);
        int pb = pg*4;
#pragma unroll 2
        for (int j = 0; j < 32; j++){
            float4 wA = wv[j*256 + oo];
            float4 wB = wv[j*256 + 128 + oo];
            ulonglong2 x0a = xq[(pb+0)*64 + 2*j], x0b = xq[(pb+0)*64 + 2*j + 1];
            ulonglong2 x1a = xq[(pb+1)*64 + 2*j], x1b = xq[(pb+1)*64 + 2*j + 1];
            ulonglong2 x2a = xq[(pb+2)*64 + 2*j], x2b = xq[(pb+2)*64 + 2*j + 1];
            ulonglong2 x3a = xq[(pb+3)*64 + 2*j], x3b = xq[(pb+3)*64 + 2*j + 1];
            unsigned long long wA0 = pk2(wA.x, wA.x), wA1 = pk2(wA.y, wA.y);
            unsigned long long wA2 = pk2(wA.z, wA.z), wA3 = pk2(wA.w, wA.w);
            a00 = fma2(wA0, x0a.x, a00); a00 = fma2(wA1, x0a.y, a00);
            a00 = fma2(wA2, x0b.x, a00); a00 = fma2(wA3, x0b.y, a00);
            a01 = fma2(wA0, x1a.x, a01); a01 = fma2(wA1, x1a.y, a01);
            a01 = fma2(wA2, x1b.x, a01); a01 = fma2(wA3, x1b.y, a01);
            a02 = fma2(wA0, x2a.x, a02); a02 = fma2(wA1, x2a.y, a02);
            a02 = fma2(wA2, x2b.x, a02); a02 = fma2(wA3, x2b.y, a02);
            a03 = fma2(wA0, x3a.x, a03); a03 = fma2(wA1, x3a.y, a03);
            a03 = fma2(wA2, x3b.x, a03); a03 = fma2(wA3, x3b.y, a03);
            unsigned long long wB0 = pk2(wB.x, wB.x), wB1 = pk2(wB.y, wB.y);
            unsigned long long wB2 = pk2(wB.z, wB.z), wB3 = pk2(wB.w, wB.w);
            a10 = fma2(wB0, x0a.x, a10); a10 = fma2(wB1, x0a.y, a10);
            a10 = fma2(wB2, x0b.x, a10); a10 = fma2(wB3, x0b.y, a10);
            a11 = fma2(wB0, x1a.x, a11); a11 = fma2(wB1, x1a.y, a11);
            a11 = fma2(wB2, x1b.x, a11); a11 = fma2(wB3, x1b.y, a11);
            a12 = fma2(wB0, x2a.x, a12); a12 = fma2(wB1, x2a.y, a12);
            a12 = fma2(wB2, x2b.x, a12); a12 = fma2(wB3, x2b.y, a12);
            a13 = fma2(wB0, x3a.x, a13); a13 = fma2(wB1, x3a.y, a13);
            a13 = fma2(wB2, x3b.x, a13); a13 = fma2(wB3, x3b.y, a13);
        }
        {
            float2 y;
            y = upk2(a00); hbp[(pb+0)*256 + oo]       = make_float2(lrelu(y.x), lrelu(y.y));
            y = upk2(a01); hbp[(pb+1)*256 + oo]       = make_float2(lrelu(y.x), lrelu(y.y));
            y = upk2(a02); hbp[(pb+2)*256 + oo]       = make_float2(lrelu(y.x), lrelu(y.y));
            y = upk2(a03); hbp[(pb+3)*256 + oo]       = make_float2(lrelu(y.x), lrelu(y.y));
            y = upk2(a10); hbp[(pb+0)*256 + 128 + oo] = make_float2(lrelu(y.x), lrelu(y.y));
            y = upk2(a11); hbp[(pb+1)*256 + 128 + oo] = make_float2(lrelu(y.x), lrelu(y.y));
            y = upk2(a12); hbp[(pb+2)*256 + 128 + oo] = make_float2(lrelu(y.x), lrelu(y.y));
            y = upk2(a13); hbp[(pb+3)*256 + 128 + oo] = make_float2(lrelu(y.x), lrelu(y.y));
        }
        __syncthreads();

        // layer 2: thread (o = t&15, part = (t>>4)&15, h = t>>8) ; 8 pairs per thread
        {
            int o = t & 15, part = (t >> 4) & 15, h = t >> 8;
            unsigned long long acc[8];
#pragma unroll
            for (int q = 0; q < 8; q++) acc[q] = 0ULL;
#pragma unroll
            for (int kk = 0; kk < 16; kk++){
                int k = part*16 + kk;
                float w2s = sm[P_W2 + k*17 + o];
                unsigned long long w2 = pk2(w2s, w2s);
#pragma unroll
                for (int q = 0; q < 8; q++)
                    acc[q] = fma2(w2, hbu[(h*8 + q)*256 + k], acc[q]);
            }
#pragma unroll
            for (int q = 0; q < 8; q++)
                sru[(h*8 + q)*256 + part*16 + o] = acc[q];
        }
        __syncthreads();

        if (t < 256){
            int pair = t >> 4, o = t & 15;
            float sx = 0.f, sy = 0.f;
#pragma unroll
            for (int p = 0; p < 16; p++){
                float2 v = srp[pair*256 + p*16 + o];
                sx += v.x; sy += v.y;
            }
            float bb2 = sm[P_B2 + o];
            g_h[(size_t)(base + 2*pair    )*16 + o] = lrelu(sx + bb2);
            g_h[(size_t)(base + 2*pair + 1)*16 + o] = lrelu(sy + bb2);
        }
        __syncthreads();
    }
}

// ---------------- per-layer: xw' = (h@W.T) * dinv ---------------------------------
__global__ void k_xw(int l){
    __shared__ float Ws[256];
    if (threadIdx.x < 256) Ws[threadIdx.x] = g_W[l*256 + threadIdx.x];
    __syncthreads();
    int n = blockIdx.x*blockDim.x + threadIdx.x;
    if (n >= NN) return;
    const float4* h4 = (const float4*)g_h;
    float4 a = h4[n*4+0], b = h4[n*4+1], c = h4[n*4+2], d = h4[n*4+3];
    float hv[16] = {a.x,a.y,a.z,a.w, b.x,b.y,b.z,b.w,
                    c.x,c.y,c.z,c.w, d.x,d.y,d.z,d.w};
    float di = g_dinv[n];
    float4* xw4 = (float4*)g_xw;
#pragma unroll
    for (int q = 0; q < 4; q++){
        float4 v;
        float* vp = (float*)&v;
#pragma unroll
        for (int r = 0; r < 4; r++){
            int o = q*4 + r;
            float acc = 0.f;
#pragma unroll
            for (int i = 0; i < 16; i++) acc += hv[i]*Ws[o*16 + i];
            vp[r] = acc * di;
        }
        xw4[n*4 + q] = v;
    }
}

// ---------------- gather layer 0: h[d] = lrelu(dinv*(sum+self)+b) ------------------
__global__ void __launch_bounds__(256)
k_gather(const float* __restrict__ gcnb, int l){
    int warp = (blockIdx.x*blockDim.x + threadIdx.x) >> 5;
    int lane = threadIdx.x & 31;
    if (warp >= NN) return;
    int node = warp;
    int slot = lane >> 2;
    int cg   = lane & 3;
    int beg = g_rowptr[node], end = g_rowptr[node + 1];
    const float4* xw4 = (const float4*)g_xw;

    float4 acc;
    if (slot == 0) acc = xw4[(size_t)node*4 + cg];
    else           acc = make_float4(0.f, 0.f, 0.f, 0.f);

    for (int j = beg + slot; j < end; j += 8){
        int s = g_csr[j];
        float4 v = xw4[(size_t)s*4 + cg];
        acc.x += v.x; acc.y += v.y; acc.z += v.z; acc.w += v.w;
    }
#pragma unroll
    for (int off = 4; off < 32; off <<= 1){
        acc.x += __shfl_xor_sync(0xffffffff, acc.x, off);
        acc.y += __shfl_xor_sync(0xffffffff, acc.y, off);
        acc.z += __shfl_xor_sync(0xffffffff, acc.z, off);
        acc.w += __shfl_xor_sync(0xffffffff, acc.w, off);
    }
    if (lane < 4){
        float di = g_dinv[node];
        const float* bp = gcnb + l*16 + cg*4;
        float4 r;
        r.x = lrelu(di*acc.x + bp[0]);
        r.y = lrelu(di*acc.y + bp[1]);
        r.z = lrelu(di*acc.z + bp[2]);
        r.w = lrelu(di*acc.w + bp[3]);
        ((float4*)g_h)[(size_t)node*4 + cg] = r;
    }
}

// ---------------- gather layer 1 + fused post heads ---------------------------------
__global__ void __launch_bounds__(256)
k_gather2(const float* __restrict__ gcnb,
          const float* __restrict__ po1W, const float* __restrict__ po1b,
          const float* __restrict__ poaW, const float* __restrict__ poab,
          float* __restrict__ out, int out_size){
    int warp = (blockIdx.x*blockDim.x + threadIdx.x) >> 5;
    int lane = threadIdx.x & 31;
    if (warp >= NN) return;
    int node = warp;
    int slot = lane >> 2;
    int cg   = lane & 3;
    int beg = g_rowptr[node], end = g_rowptr[node + 1];
    const float4* xw4 = (const float4*)g_xw;

    float4 acc;
    if (slot == 0) acc = xw4[(size_t)node*4 + cg];
    else           acc = make_float4(0.f, 0.f, 0.f, 0.f);

    for (int j = beg + slot; j < end; j += 8){
        int s = g_csr[j];
        float4 v = xw4[(size_t)s*4 + cg];
        acc.x += v.x; acc.y += v.y; acc.z += v.z; acc.w += v.w;
    }
#pragma unroll
    for (int off = 4; off < 32; off <<= 1){
        acc.x += __shfl_xor_sync(0xffffffff, acc.x, off);
        acc.y += __shfl_xor_sync(0xffffffff, acc.y, off);
        acc.z += __shfl_xor_sync(0xffffffff, acc.z, off);
        acc.w += __shfl_xor_sync(0xffffffff, acc.w, off);
    }
    if (lane < 4){
        float di = g_dinv[node];
        const float* bp = gcnb + 16 + cg*4;   // l = 1
        float4 r;
        r.x = lrelu(di*acc.x + bp[0]);
        r.y = lrelu(di*acc.y + bp[1]);
        r.z = lrelu(di*acc.z + bp[2]);
        r.w = lrelu(di*acc.w + bp[3]);
        if (out_size >= 18*NN)
            ((float4*)(out + 2*NN))[(size_t)node*4 + cg] = r;
        int c0 = cg*4;
        float sp = r.x*(po1W[c0+0] + po1W[16+c0+0])
                 + r.y*(po1W[c0+1] + po1W[16+c0+1])
                 + r.z*(po1W[c0+2] + po1W[16+c0+2])
                 + r.w*(po1W[c0+3] + po1W[16+c0+3]);
        float ap = r.x*poaW[c0+0] + r.y*poaW[c0+1]
                 + r.z*poaW[c0+2] + r.w*poaW[c0+3];
        unsigned qm = 0xFu << ((lane >> 2) << 2);
        sp += __shfl_xor_sync(qm, sp, 1); sp += __shfl_xor_sync(qm, sp, 2);
        ap += __shfl_xor_sync(qm, ap, 1); ap += __shfl_xor_sync(qm, ap, 2);
        if (cg == 0){
            out[node] = sp + po1b[0] + po1b[1];
            if (out_size >= 2*NN) out[NN + node] = ap + poab[0];
        }
    }
}

// ---------------- launch --------------------------------------------------------------
extern "C" void kernel_launch(void* const* d_in, const int* in_sizes, int n_in,
                              void* d_out, int out_size){
    const float* x    = (const float*)d_in[0];
    const int*   ei32 = (const int*)d_in[1];
    const float* p1W  = (const float*)d_in[2];
    const float* p1b  = (const float*)d_in[3];
    const float* p2W  = (const float*)d_in[4];
    const float* p2b  = (const float*)d_in[5];
    const float* bih  = (const float*)d_in[6];
    const float* bhh  = (const float*)d_in[7];
    const float* wtW  = (const float*)d_in[8];
    const float* wtb  = (const float*)d_in[9];
    const float* gcnb = (const float*)d_in[10];
    const float* po1W = (const float*)d_in[11];
    const float* po1b = (const float*)d_in[12];
    const float* poaW = (const float*)d_in[13];
    const float* poab = (const float*)d_in[14];
    float* out = (float*)d_out;

    cudaFuncSetAttribute(k_pre, cudaFuncAttributeMaxDynamicSharedMemorySize,
                         PRE_SMEM_BYTES);

    const int NB_N = (NN + 255)/256;
    const int NB_E = (NE + 255)/256;
    const int NB_E2 = (NE/2 + 255)/256;
    const int NB_SCAN = (NN + 4095)/4096;   // 25
    const int NB_G = (NN*32 + 255)/256;     // warp per node
    const int NB_I = 2 + (NN + 511)/512;    // init: detect + hyper + cnt0

    // launch index:        0       1        2        3 (profiled slot)
    k_init  <<<NB_I, 512>>>(ei32, bih, bhh, wtW, wtb);
    k_edges <<<NB_E2, 256>>>(ei32);
    k_scan1 <<<NB_SCAN, 512>>>();
    k_pre   <<<148, 512, PRE_SMEM_BYTES>>>(x, p1W, p1b, p2W, p2b);
    // 4..
    k_scan2 <<<1, 32>>>(NB_SCAN);
    k_scan3 <<<NB_N, 256>>>();
    k_fill  <<<NB_E, 256>>>(ei32);
    k_xw     <<<NB_N, 256>>>(0);
    k_gather <<<NB_G, 256>>>(gcnb, 0);
    k_xw     <<<NB_N, 256>>>(1);
    k_gather2<<<NB_G, 256>>>(gcnb, po1W, po1b, poaW, poab, out, out_size);
}